// round 1
// baseline (speedup 1.0000x reference)
#include <cuda_runtime.h>

#define N_STATE 131072
#define H 128

// Scratch (device globals — no allocation allowed)
__device__ float g_y[H];   // y = W0 @ x_norm
__device__ float g_r[H];   // collapsed backward vector

// ---------------------------------------------------------------------------
// Kernel A: y[row] = sum_n W0[row, n] * x_norm[n]
// x_norm computed on the fly: (2 s - mx - mn) / (mx - mn)
// One block per row of W0 (128 blocks x 1024 threads). HBM-bound on W0.
// ---------------------------------------------------------------------------
__global__ __launch_bounds__(1024, 1)
void k_fwd_matvec(const float* __restrict__ state,
                  const float* __restrict__ xmax,
                  const float* __restrict__ xmin,
                  const float* __restrict__ W0)
{
    const int row = blockIdx.x;
    const float4* __restrict__ w   = (const float4*)(W0 + (size_t)row * N_STATE);
    const float4* __restrict__ s4  = (const float4*)state;
    const float4* __restrict__ mx4 = (const float4*)xmax;
    const float4* __restrict__ mn4 = (const float4*)xmin;

    const int nvec = N_STATE / 4;
    float acc = 0.0f;
    for (int i = threadIdx.x; i < nvec; i += blockDim.x) {
        float4 wv = w[i];
        float4 s  = s4[i];
        float4 mx = mx4[i];
        float4 mn = mn4[i];
        float xn0 = (2.0f * s.x - mx.x - mn.x) / (mx.x - mn.x);
        float xn1 = (2.0f * s.y - mx.y - mn.y) / (mx.y - mn.y);
        float xn2 = (2.0f * s.z - mx.z - mn.z) / (mx.z - mn.z);
        float xn3 = (2.0f * s.w - mx.w - mn.w) / (mx.w - mn.w);
        acc += wv.x * xn0 + wv.y * xn1 + wv.z * xn2 + wv.w * xn3;
    }

    // block reduce
    __shared__ float red[32];
    #pragma unroll
    for (int o = 16; o > 0; o >>= 1)
        acc += __shfl_down_sync(0xffffffffu, acc, o);
    if ((threadIdx.x & 31) == 0) red[threadIdx.x >> 5] = acc;
    __syncthreads();
    if (threadIdx.x < 32) {
        float v = (threadIdx.x < (blockDim.x >> 5)) ? red[threadIdx.x] : 0.0f;
        #pragma unroll
        for (int o = 16; o > 0; o >>= 1)
            v += __shfl_down_sync(0xffffffffu, v, o);
        if (threadIdx.x == 0) g_y[row] = v;
    }
}

// ---------------------------------------------------------------------------
// Kernel B: tiny serial core. One block, 128 threads.
//   Forward: V0=tanh(y+b0), V1=tanh(W1 V0+b1), V2=tanh(W2 V1+b2),
//            V3=W3 V2+b3, Vout = Wout.V3 + bout  -> out[0]
//   Backward: r^T = Wout W3 D2 W2 D1 W1 D0        -> g_r
// ---------------------------------------------------------------------------
__global__ __launch_bounds__(128, 1)
void k_core(const float* __restrict__ b0,
            const float* __restrict__ W1, const float* __restrict__ b1,
            const float* __restrict__ W2, const float* __restrict__ b2,
            const float* __restrict__ W3, const float* __restrict__ b3,
            const float* __restrict__ Wout, const float* __restrict__ bout,
            float* __restrict__ out)
{
    __shared__ float v[H];
    __shared__ float t[H];
    __shared__ float d0[H], d1[H], d2[H];
    __shared__ float red[4];

    const int j = threadIdx.x;

    // input activation
    float V0 = tanhf(g_y[j] + b0[j]);
    d0[j] = 1.0f - V0 * V0;
    v[j] = V0;
    __syncthreads();

    // layer 0: W1, tanh
    float acc = b1[j];
    #pragma unroll 8
    for (int k = 0; k < H; k++) acc += W1[j * H + k] * v[k];
    float V1 = tanhf(acc);
    d1[j] = 1.0f - V1 * V1;
    __syncthreads();
    v[j] = V1;
    __syncthreads();

    // layer 1: W2, tanh
    acc = b2[j];
    #pragma unroll 8
    for (int k = 0; k < H; k++) acc += W2[j * H + k] * v[k];
    float V2 = tanhf(acc);
    d2[j] = 1.0f - V2 * V2;
    __syncthreads();
    v[j] = V2;
    __syncthreads();

    // layer 2: W3, no activation
    acc = b3[j];
    #pragma unroll 8
    for (int k = 0; k < H; k++) acc += W3[j * H + k] * v[k];
    __syncthreads();
    v[j] = acc;
    __syncthreads();

    // output scalar: Vout = sum_j Wout[j] * v[j] + bout
    float p = Wout[j] * v[j];
    #pragma unroll
    for (int o = 16; o > 0; o >>= 1)
        p += __shfl_down_sync(0xffffffffu, p, o);
    if ((j & 31) == 0) red[j >> 5] = p;
    __syncthreads();
    if (j == 0)
        out[0] = red[0] + red[1] + red[2] + red[3] + bout[0];

    // backward: r^T = Wout W3 D2 W2 D1 W1 D0
    t[j] = Wout[j];
    __syncthreads();

    acc = 0.0f;                                  // (t^T W3)_j, then * d2
    #pragma unroll 8
    for (int i = 0; i < H; i++) acc += t[i] * W3[i * H + j];
    acc *= d2[j];
    __syncthreads();
    t[j] = acc;
    __syncthreads();

    acc = 0.0f;                                  // (t^T W2)_j, then * d1
    #pragma unroll 8
    for (int i = 0; i < H; i++) acc += t[i] * W2[i * H + j];
    acc *= d1[j];
    __syncthreads();
    t[j] = acc;
    __syncthreads();

    acc = 0.0f;                                  // (t^T W1)_j, then * d0
    #pragma unroll 8
    for (int i = 0; i < H; i++) acc += t[i] * W1[i * H + j];
    acc *= d0[j];
    g_r[j] = acc;
}

// ---------------------------------------------------------------------------
// Kernel C: JV[n] = (sum_i r[i] * W0[i, n]) * 2 / (xmax[n] - xmin[n])
// Each thread owns one float4 of n. Columns accessed row-by-row, coalesced.
// W0 should still be L2-resident from kernel A (64 MiB < ~126 MB L2).
// ---------------------------------------------------------------------------
__global__ __launch_bounds__(256, 4)
void k_jv(const float* __restrict__ W0,
          const float* __restrict__ xmax,
          const float* __restrict__ xmin,
          float* __restrict__ out)
{
    __shared__ float r[H];
    if (threadIdx.x < H) r[threadIdx.x] = g_r[threadIdx.x];
    __syncthreads();

    const int n4 = blockIdx.x * blockDim.x + threadIdx.x;   // float4 index
    const float4* __restrict__ w = (const float4*)W0;
    const int stride4 = N_STATE / 4;

    float ax = 0.0f, ay = 0.0f, az = 0.0f, aw = 0.0f;
    #pragma unroll 8
    for (int i = 0; i < H; i++) {
        float4 wv = w[(size_t)i * stride4 + n4];
        float ri = r[i];
        ax += ri * wv.x;
        ay += ri * wv.y;
        az += ri * wv.z;
        aw += ri * wv.w;
    }

    float4 mx = ((const float4*)xmax)[n4];
    float4 mn = ((const float4*)xmin)[n4];
    const int n = n4 * 4;
    out[1 + n + 0] = ax * (2.0f / (mx.x - mn.x));
    out[1 + n + 1] = ay * (2.0f / (mx.y - mn.y));
    out[1 + n + 2] = az * (2.0f / (mx.z - mn.z));
    out[1 + n + 3] = aw * (2.0f / (mx.w - mn.w));
}

// ---------------------------------------------------------------------------
extern "C" void kernel_launch(void* const* d_in, const int* in_sizes, int n_in,
                              void* d_out, int out_size)
{
    const float* state = (const float*)d_in[0];
    const float* xmax  = (const float*)d_in[1];
    const float* xmin  = (const float*)d_in[2];
    const float* W0    = (const float*)d_in[3];
    const float* b0    = (const float*)d_in[4];
    const float* W1    = (const float*)d_in[5];
    const float* b1    = (const float*)d_in[6];
    const float* W2    = (const float*)d_in[7];
    const float* b2    = (const float*)d_in[8];
    const float* W3    = (const float*)d_in[9];
    const float* b3    = (const float*)d_in[10];
    const float* Wout  = (const float*)d_in[11];
    const float* bout  = (const float*)d_in[12];
    float* out = (float*)d_out;

    k_fwd_matvec<<<H, 1024>>>(state, xmax, xmin, W0);
    k_core<<<1, H>>>(b0, W1, b1, W2, b2, W3, b3, Wout, bout, out);
    k_jv<<<(N_STATE / 4) / 256, 256>>>(W0, xmax, xmin, out);
}

// round 3
// speedup vs baseline: 1.1969x; 1.1969x over previous
#include <cuda_runtime.h>

#define N_STATE 131072
#define H 128
#define SEG 32          // n-segments in kernel A
#define RPB 8           // rows per block in kernel A

// Scratch (device globals — no allocation allowed)
__device__ float g_xnorm[N_STATE];
__device__ float g_scale[N_STATE];
__device__ float g_ypart[SEG * H];
__device__ float g_r[H];

// ---------------------------------------------------------------------------
// Kernel N: x_norm[n] = (2 s - mx - mn) / (mx - mn);  scale[n] = 2/(mx - mn)
// ---------------------------------------------------------------------------
__global__ __launch_bounds__(256)
void k_norm(const float* __restrict__ state,
            const float* __restrict__ xmax,
            const float* __restrict__ xmin)
{
    const int i = blockIdx.x * blockDim.x + threadIdx.x;   // float4 index
    float4 s  = ((const float4*)state)[i];
    float4 mx = ((const float4*)xmax)[i];
    float4 mn = ((const float4*)xmin)[i];
    float4 inv, xn, sc;
    inv.x = 1.0f / (mx.x - mn.x);
    inv.y = 1.0f / (mx.y - mn.y);
    inv.z = 1.0f / (mx.z - mn.z);
    inv.w = 1.0f / (mx.w - mn.w);
    xn.x = (2.0f * s.x - mx.x - mn.x) * inv.x;
    xn.y = (2.0f * s.y - mx.y - mn.y) * inv.y;
    xn.z = (2.0f * s.z - mx.z - mn.z) * inv.z;
    xn.w = (2.0f * s.w - mx.w - mn.w) * inv.w;
    sc.x = 2.0f * inv.x;  sc.y = 2.0f * inv.y;
    sc.z = 2.0f * inv.z;  sc.w = 2.0f * inv.w;
    ((float4*)g_xnorm)[i] = xn;
    ((float4*)g_scale)[i] = sc;
}

// ---------------------------------------------------------------------------
// Kernel A: partial y. blockIdx.x = segment (0..SEG-1), blockIdx.y = rowgroup.
// Each block: RPB rows x (N/SEG) columns. x_norm chunk reused across RPB rows.
// ---------------------------------------------------------------------------
__global__ __launch_bounds__(256, 4)
void k_fwd_matvec(const float* __restrict__ W0)
{
    const int seg = blockIdx.x;
    const int row0 = blockIdx.y * RPB;
    const int chunk4 = (N_STATE / SEG) / 4;                // float4s per segment

    const float4* __restrict__ xn = (const float4*)g_xnorm + (size_t)seg * chunk4;
    const float4* __restrict__ w0 = (const float4*)(W0 + (size_t)row0 * N_STATE) + (size_t)seg * chunk4;
    const size_t rstride4 = N_STATE / 4;

    float acc[RPB];
    #pragma unroll
    for (int r = 0; r < RPB; r++) acc[r] = 0.0f;

    for (int i = threadIdx.x; i < chunk4; i += blockDim.x) {
        float4 x = xn[i];
        #pragma unroll
        for (int r = 0; r < RPB; r++) {
            float4 wv = w0[(size_t)r * rstride4 + i];
            acc[r] += wv.x * x.x + wv.y * x.y + wv.z * x.z + wv.w * x.w;
        }
    }

    __shared__ float red[8][RPB];
    const int lane = threadIdx.x & 31, warp = threadIdx.x >> 5;
    #pragma unroll
    for (int r = 0; r < RPB; r++) {
        float v = acc[r];
        #pragma unroll
        for (int o = 16; o > 0; o >>= 1)
            v += __shfl_down_sync(0xffffffffu, v, o);
        if (lane == 0) red[warp][r] = v;
    }
    __syncthreads();
    if (threadIdx.x < RPB) {
        float v = 0.0f;
        #pragma unroll
        for (int w = 0; w < 8; w++) v += red[w][threadIdx.x];
        g_ypart[seg * H + row0 + threadIdx.x] = v;
    }
}

// ---------------------------------------------------------------------------
// Kernel B: sum partials -> y, forward tanh chain, backward collapse -> g_r.
// One block, 128 threads.
// ---------------------------------------------------------------------------
__global__ __launch_bounds__(128, 1)
void k_core(const float* __restrict__ b0,
            const float* __restrict__ W1, const float* __restrict__ b1,
            const float* __restrict__ W2, const float* __restrict__ b2,
            const float* __restrict__ W3, const float* __restrict__ b3,
            const float* __restrict__ Wout, const float* __restrict__ bout,
            float* __restrict__ out)
{
    __shared__ float v[H];
    __shared__ float t[H];
    __shared__ float d0[H], d1[H], d2[H];
    __shared__ float red[4];

    const int j = threadIdx.x;

    // y[j] = sum of segment partials
    float y = 0.0f;
    #pragma unroll
    for (int s = 0; s < SEG; s++) y += g_ypart[s * H + j];

    // input activation
    float V0 = tanhf(y + b0[j]);
    d0[j] = 1.0f - V0 * V0;
    v[j] = V0;
    __syncthreads();

    // layer 0: W1, tanh
    float acc = b1[j];
    #pragma unroll 8
    for (int k = 0; k < H; k++) acc += W1[j * H + k] * v[k];
    float V1 = tanhf(acc);
    d1[j] = 1.0f - V1 * V1;
    __syncthreads();
    v[j] = V1;
    __syncthreads();

    // layer 1: W2, tanh
    acc = b2[j];
    #pragma unroll 8
    for (int k = 0; k < H; k++) acc += W2[j * H + k] * v[k];
    float V2 = tanhf(acc);
    d2[j] = 1.0f - V2 * V2;
    __syncthreads();
    v[j] = V2;
    __syncthreads();

    // layer 2: W3, no activation
    acc = b3[j];
    #pragma unroll 8
    for (int k = 0; k < H; k++) acc += W3[j * H + k] * v[k];
    __syncthreads();
    v[j] = acc;
    __syncthreads();

    // output scalar
    float p = Wout[j] * v[j];
    #pragma unroll
    for (int o = 16; o > 0; o >>= 1)
        p += __shfl_down_sync(0xffffffffu, p, o);
    if ((j & 31) == 0) red[j >> 5] = p;
    __syncthreads();
    if (j == 0)
        out[0] = red[0] + red[1] + red[2] + red[3] + bout[0];

    // backward: r^T = Wout W3 D2 W2 D1 W1 D0
    t[j] = Wout[j];
    __syncthreads();

    acc = 0.0f;
    #pragma unroll 8
    for (int i = 0; i < H; i++) acc += t[i] * W3[i * H + j];
    acc *= d2[j];
    __syncthreads();
    t[j] = acc;
    __syncthreads();

    acc = 0.0f;
    #pragma unroll 8
    for (int i = 0; i < H; i++) acc += t[i] * W2[i * H + j];
    acc *= d1[j];
    __syncthreads();
    t[j] = acc;
    __syncthreads();

    acc = 0.0f;
    #pragma unroll 8
    for (int i = 0; i < H; i++) acc += t[i] * W1[i * H + j];
    acc *= d0[j];
    g_r[j] = acc;
}

// ---------------------------------------------------------------------------
// Kernel C: JV[n] = scale[n] * sum_i r[i] * W0[i, n]
// 256 blocks x 256 threads, float2 per thread, i-loop unrolled for MLP.
// ---------------------------------------------------------------------------
__global__ __launch_bounds__(256, 4)
void k_jv(const float* __restrict__ W0, float* __restrict__ out)
{
    __shared__ float r[H];
    if (threadIdx.x < H) r[threadIdx.x] = g_r[threadIdx.x];
    __syncthreads();

    const int n2 = blockIdx.x * blockDim.x + threadIdx.x;   // float2 index
    const float2* __restrict__ w = (const float2*)W0;
    const size_t stride2 = N_STATE / 2;

    float ax = 0.0f, ay = 0.0f;
    #pragma unroll 16
    for (int i = 0; i < H; i++) {
        float2 wv = w[(size_t)i * stride2 + n2];
        float ri = r[i];
        ax += ri * wv.x;
        ay += ri * wv.y;
    }

    float2 sc = ((const float2*)g_scale)[n2];
    const int n = n2 * 2;
    out[1 + n + 0] = ax * sc.x;
    out[1 + n + 1] = ay * sc.y;
}

// ---------------------------------------------------------------------------
extern "C" void kernel_launch(void* const* d_in, const int* in_sizes, int n_in,
                              void* d_out, int out_size)
{
    const float* state = (const float*)d_in[0];
    const float* xmax  = (const float*)d_in[1];
    const float* xmin  = (const float*)d_in[2];
    const float* W0    = (const float*)d_in[3];
    const float* b0    = (const float*)d_in[4];
    const float* W1    = (const float*)d_in[5];
    const float* b1    = (const float*)d_in[6];
    const float* W2    = (const float*)d_in[7];
    const float* b2    = (const float*)d_in[8];
    const float* W3    = (const float*)d_in[9];
    const float* b3    = (const float*)d_in[10];
    const float* Wout  = (const float*)d_in[11];
    const float* bout  = (const float*)d_in[12];
    float* out = (float*)d_out;

    k_norm<<<N_STATE / 4 / 256, 256>>>(state, xmax, xmin);
    dim3 gridA(SEG, H / RPB);
    k_fwd_matvec<<<gridA, 256>>>(W0);
    k_core<<<1, H>>>(b0, W1, b1, W2, b2, W3, b3, Wout, bout, out);
    k_jv<<<(N_STATE / 2) / 256, 256>>>(W0, out);
}